// round 5
// baseline (speedup 1.0000x reference)
#include <cuda_runtime.h>
#include <math_constants.h>

// Problem constants (fixed by reference: B=4, S=1024, D=512, COMP=4)
#define BATCH   4
#define SEQ     1024
#define DIM     512
#define NCOMP   (SEQ / 4)          // 256
#define STEPS   (SEQ - NCOMP)      // 768
#define NBLK    (SEQ / 32)         // 32 blocks of 32 dot entries

// Mutable working copy + scratch (no allocs allowed in kernel_launch)
__device__ float    g_x[BATCH * SEQ * DIM];
__device__ unsigned g_dotord[BATCH * SEQ];
__device__ int      g_order[BATCH * NCOMP];

// order-preserving float -> uint map (monotonic: a<b  <=>  f2ord(a)<f2ord(b))
__device__ __forceinline__ unsigned f2ord(float f) {
    unsigned u = __float_as_uint(f);
    return (u >> 31) ? ~u : (u | 0x80000000u);
}

// ---------------- copy input to mutable scratch ----------------
__global__ void copy_in_kernel(const float* __restrict__ in) {
    const float4* in4 = (const float4*)in;
    float4* out4 = (float4*)g_x;
    const int n4 = BATCH * SEQ * DIM / 4;
    for (int i = blockIdx.x * blockDim.x + threadIdx.x; i < n4;
         i += gridDim.x * blockDim.x)
        out4[i] = in4[i];
}

// ---------------- initial adjacent dots (one warp per dot, parallel) ----------------
__global__ void init_dots_kernel(const float* __restrict__ in) {
    int w = (blockIdx.x * blockDim.x + threadIdx.x) >> 5;
    int lane = threadIdx.x & 31;
    if (w >= BATCH * SEQ) return;
    int b = w / SEQ, j = w % SEQ;
    unsigned o;
    if (j == SEQ - 1) {
        o = 0u;  // absolute minimum in ord space
    } else {
        const float4* a = (const float4*)(in + ((size_t)b * SEQ + j) * DIM);
        const float4* c = (const float4*)(in + ((size_t)b * SEQ + j + 1) * DIM);
        float acc = 0.f;
        #pragma unroll
        for (int k = 0; k < 4; k++) {
            float4 av = a[k * 32 + lane];
            float4 cv = c[k * 32 + lane];
            acc += av.x * cv.x + av.y * cv.y + av.z * cv.z + av.w * cv.w;
        }
        #pragma unroll
        for (int of = 16; of; of >>= 1) acc += __shfl_xor_sync(0xffffffffu, acc, of);
        o = f2ord(acc);
    }
    if (lane == 0) g_dotord[b * SEQ + j] = o;
}

// ---------------- single-warp merge state machine (one per sample) ----------------
__global__ __launch_bounds__(32)
void merge_kernel() {
    __shared__ unsigned s_dotord[SEQ];   // adjacent dots, ord-mapped
    __shared__ short    s_nxt[SEQ];
    __shared__ short    s_prv[SEQ];
    __shared__ unsigned s_bm[NBLK];      // block maxima (ord) — kept FRESH at every commit
    __shared__ int      s_bi[NBLK];      // block argmax (global entry index)

    const unsigned FULL = 0xffffffffu;
    const int lane = threadIdx.x;
    const int b = blockIdx.x;
    float* x = g_x + (size_t)b * SEQ * DIM;

    #pragma unroll
    for (int k = 0; k < SEQ / 32; k++) {
        int i = k * 32 + lane;
        s_dotord[i] = g_dotord[b * SEQ + i];
        s_nxt[i] = (short)((i == SEQ - 1) ? -1 : i + 1);
        s_prv[i] = (short)(i - 1);
    }
    __syncwarp();

    // build block maxima
    for (int blk = 0; blk < NBLK; blk++) {
        unsigned d = s_dotord[blk * 32 + lane];
        unsigned m = __reduce_max_sync(FULL, d);
        unsigned bal = __ballot_sync(FULL, d == m);
        if (lane == 0) { s_bm[blk] = m; s_bi[blk] = blk * 32 + __ffs(bal) - 1; }
    }
    __syncwarp();

    // initial global argmax
    int mid;
    {
        unsigned v = s_bm[lane];
        int vb = s_bi[lane];
        unsigned M = __reduce_max_sync(FULL, v);
        unsigned bal = __ballot_sync(FULL, v == M);
        mid = __shfl_sync(FULL, vb, __ffs(bal) - 1);
    }

    for (int t = 0; t < STEPS; t++) {
        const int nxt  = s_nxt[mid];
        const int prev = s_prv[mid];
        const int nn   = s_nxt[nxt];

        // ---- issue all row loads up front (scans below run under the L2 shadow) ----
        const float4* rm = (const float4*)(x + (size_t)mid * DIM);
        const float4* rn = (const float4*)(x + (size_t)nxt * DIM);
        const float4* rp = (prev >= 0) ? (const float4*)(x + (size_t)prev * DIM) : rm;
        const float4* rq = (nn   >= 0) ? (const float4*)(x + (size_t)nn   * DIM) : rm;
        float4 vm[4], vn[4], vp[4], vq[4];
        #pragma unroll
        for (int c = 0; c < 4; c++) {
            vm[c] = rm[c * 32 + lane];
            vn[c] = rn[c * 32 + lane];
            vp[c] = rp[c * 32 + lane];
            vq[c] = rq[c * 32 + lane];
        }

        // ---- masked rescan of DISTINCT dirty blocks (under shadow) ----
        const int dbm = mid >> 5;
        const int dbp = (prev >= 0 ? prev : mid) >> 5;
        const int dbn = nxt >> 5;
        const bool haveP = (dbp != dbm);
        const bool haveN = (dbn != dbm) && (dbn != dbp);

        unsigned mM, mP = 0u, mN = 0u; int iM, iP = 0, iN = 0;
        {
            int e = dbm * 32 + lane;
            unsigned d = s_dotord[e];
            if (e == prev || e == mid || e == nxt) d = 0u;
            mM = __reduce_max_sync(FULL, d);
            unsigned bal = __ballot_sync(FULL, d == mM);
            iM = dbm * 32 + __ffs(bal) - 1;
        }
        if (haveP) {
            int e = dbp * 32 + lane;
            unsigned d = s_dotord[e];
            if (e == prev || e == mid || e == nxt) d = 0u;
            mP = __reduce_max_sync(FULL, d);
            unsigned bal = __ballot_sync(FULL, d == mP);
            iP = dbp * 32 + __ffs(bal) - 1;
        }
        if (haveN) {
            int e = dbn * 32 + lane;
            unsigned d = s_dotord[e];
            if (e == prev || e == mid || e == nxt) d = 0u;
            mN = __reduce_max_sync(FULL, d);
            unsigned bal = __ballot_sync(FULL, d == mN);
            iN = dbn * 32 + __ffs(bal) - 1;
        }

        // ---- scan block-max table, masking the dirty blocks (under shadow) ----
        unsigned sbv; int sbi;
        {
            unsigned v = s_bm[lane];
            int vb = s_bi[lane];
            if (lane == dbp || lane == dbm || lane == dbn) v = 0u;
            unsigned M = __reduce_max_sync(FULL, v);
            unsigned bal = __ballot_sync(FULL, v == M);
            sbi = __shfl_sync(FULL, vb, __ffs(bal) - 1);
            sbv = M;
        }

        // ---- merge math (bitwise-identical expressions to the passing kernels) ----
        float p1 = 0.f, p2 = 0.f;
        float4 nv[4];
        #pragma unroll
        for (int c = 0; c < 4; c++) {
            nv[c].x = 0.5f * (vm[c].x + vn[c].x);
            nv[c].y = 0.5f * (vm[c].y + vn[c].y);
            nv[c].z = 0.5f * (vm[c].z + vn[c].z);
            nv[c].w = 0.5f * (vm[c].w + vn[c].w);
            p1 += vp[c].x * nv[c].x + vp[c].y * nv[c].y + vp[c].z * nv[c].z + vp[c].w * nv[c].w;
            p2 += nv[c].x * vq[c].x + nv[c].y * vq[c].y + nv[c].z * vq[c].z + nv[c].w * vq[c].w;
        }
        float4* wrow = (float4*)(x + (size_t)mid * DIM);
        #pragma unroll
        for (int c = 0; c < 4; c++) wrow[c * 32 + lane] = nv[c];

        #pragma unroll
        for (int o = 16; o; o >>= 1) {
            p1 += __shfl_xor_sync(FULL, p1, o);
            p2 += __shfl_xor_sync(FULL, p2, o);
        }

        // ---- fold new entries into the dirty-block maxima (exact, uniform) ----
        const unsigned p1o = f2ord(p1);
        const unsigned p2o = f2ord(p2);

        unsigned c0 = mM; int c0i = iM;                  // block dbm (always contains mid)
        if (nn >= 0 && (p2o > c0 || (p2o == c0 && mid < c0i))) { c0 = p2o; c0i = mid; }
        if (prev >= 0 && dbp == dbm &&
            (p1o > c0 || (p1o == c0 && prev < c0i)))     { c0 = p1o; c0i = prev; }
        unsigned c1 = mP; int c1i = iP;                  // block dbp (distinct => prev >= 0)
        if (haveP && (p1o > c1 || (p1o == c1 && prev < c1i))) { c1 = p1o; c1i = prev; }

        // ---- next global argmax: masked table scan + fresh dirty-block candidates ----
        unsigned nbv = sbv; int nmid = sbi;
        if (c0 > nbv || (c0 == nbv && c0i < nmid)) { nbv = c0; nmid = c0i; }
        if (haveP && (c1 > nbv || (c1 == nbv && c1i < nmid))) { nbv = c1; nmid = c1i; }
        if (haveN && (mN > nbv || (mN == nbv && iN < nmid))) { nbv = mN; nmid = iN; }

        // ---- commit: dot table, links, and FRESH block maxima ----
        if (lane == 0) {
            if (prev >= 0) s_dotord[prev] = p1o;
            s_dotord[mid] = (nn >= 0) ? p2o : 0u;
            s_dotord[nxt] = 0u;
            s_nxt[mid] = (short)nn;
            if (nn >= 0) s_prv[nn] = (short)mid;
            s_bm[dbm] = c0; s_bi[dbm] = c0i;
            if (haveP) { s_bm[dbp] = c1; s_bi[dbp] = c1i; }
            if (haveN) { s_bm[dbn] = mN; s_bi[dbn] = iN; }
        }
        __syncwarp();

        mid = nmid;
    }

    // survivor order (head 0 is never removed — removed rows are always 'nxt')
    if (lane == 0) {
        int idx = 0;
        for (int c = 0; c < NCOMP; c++) { g_order[b * NCOMP + c] = idx; idx = s_nxt[idx]; }
    }
}

// ---------------- gather survivors to output (parallel) ----------------
__global__ void gather_kernel(float* __restrict__ out) {
    int r = blockIdx.x;                 // 0 .. BATCH*NCOMP-1
    int b = r / NCOMP;
    int src = g_order[r];
    const float4* s = (const float4*)(g_x + ((size_t)b * SEQ + src) * DIM);
    float4* d = (float4*)(out + (size_t)r * DIM);
    d[threadIdx.x] = s[threadIdx.x];    // 128 threads x float4 = 512 floats
}

extern "C" void kernel_launch(void* const* d_in, const int* in_sizes, int n_in,
                              void* d_out, int out_size) {
    const float* x = (const float*)d_in[0];
    float* out = (float*)d_out;
    copy_in_kernel<<<256, 256>>>(x);
    init_dots_kernel<<<(BATCH * SEQ * 32) / 256, 256>>>(x);
    merge_kernel<<<BATCH, 32>>>();
    gather_kernel<<<BATCH * NCOMP, 128>>>(out);
}

// round 6
// speedup vs baseline: 1.5373x; 1.5373x over previous
#include <cuda_runtime.h>
#include <math_constants.h>

// Problem constants (fixed by reference: B=4, S=1024, D=512, COMP=4)
#define BATCH   4
#define SEQ     1024
#define DIM     512
#define NCOMP   (SEQ / 4)          // 256
#define STEPS   (SEQ - NCOMP)      // 768
#define NBLK    (SEQ / 32)         // 32 blocks of 32 dot entries

// Mutable working copy + scratch (no allocs allowed in kernel_launch)
__device__ float    g_x[BATCH * SEQ * DIM];
__device__ unsigned g_dotord[BATCH * SEQ];
__device__ int      g_order[BATCH * NCOMP];

// order-preserving float -> uint map (monotonic: a<b  <=>  f2ord(a)<f2ord(b))
__device__ __forceinline__ unsigned f2ord(float f) {
    unsigned u = __float_as_uint(f);
    return (u >> 31) ? ~u : (u | 0x80000000u);
}

// ---------------- copy input to mutable scratch ----------------
__global__ void copy_in_kernel(const float* __restrict__ in) {
    const float4* in4 = (const float4*)in;
    float4* out4 = (float4*)g_x;
    const int n4 = BATCH * SEQ * DIM / 4;
    for (int i = blockIdx.x * blockDim.x + threadIdx.x; i < n4;
         i += gridDim.x * blockDim.x)
        out4[i] = in4[i];
}

// ---------------- initial adjacent dots (one warp per dot, parallel) ----------------
__global__ void init_dots_kernel(const float* __restrict__ in) {
    int w = (blockIdx.x * blockDim.x + threadIdx.x) >> 5;
    int lane = threadIdx.x & 31;
    if (w >= BATCH * SEQ) return;
    int b = w / SEQ, j = w % SEQ;
    unsigned o;
    if (j == SEQ - 1) {
        o = 0u;  // absolute minimum in ord space
    } else {
        const float4* a = (const float4*)(in + ((size_t)b * SEQ + j) * DIM);
        const float4* c = (const float4*)(in + ((size_t)b * SEQ + j + 1) * DIM);
        float acc = 0.f;
        #pragma unroll
        for (int k = 0; k < 4; k++) {
            float4 av = a[k * 32 + lane];
            float4 cv = c[k * 32 + lane];
            acc += av.x * cv.x + av.y * cv.y + av.z * cv.z + av.w * cv.w;
        }
        #pragma unroll
        for (int of = 16; of; of >>= 1) acc += __shfl_xor_sync(0xffffffffu, acc, of);
        o = f2ord(acc);
    }
    if (lane == 0) g_dotord[b * SEQ + j] = o;
}

// ---------------- single-warp merge state machine (one per sample) ----------------
__global__ __launch_bounds__(32)
void merge_kernel() {
    __shared__ unsigned s_dotord[SEQ];   // adjacent dots, ord-mapped
    __shared__ short    s_nxt[SEQ];
    __shared__ short    s_prv[SEQ];
    __shared__ unsigned s_bm[NBLK];      // block maxima (ord); stale only for sb0..sb2
    __shared__ int      s_bi[NBLK];      // block argmax (global entry index)

    const unsigned FULL = 0xffffffffu;
    const int lane = threadIdx.x;
    const int b = blockIdx.x;
    float* x = g_x + (size_t)b * SEQ * DIM;

    #pragma unroll
    for (int k = 0; k < SEQ / 32; k++) {
        int i = k * 32 + lane;
        s_dotord[i] = g_dotord[b * SEQ + i];
        s_nxt[i] = (short)((i == SEQ - 1) ? -1 : i + 1);
        s_prv[i] = (short)(i - 1);
    }
    __syncwarp();

    // build block maxima (fresh)
    for (int blk = 0; blk < NBLK; blk++) {
        unsigned d = s_dotord[blk * 32 + lane];
        unsigned m = __reduce_max_sync(FULL, d);
        unsigned bal = __ballot_sync(FULL, d == m);
        if (lane == 0) { s_bm[blk] = m; s_bi[blk] = blk * 32 + __ffs(bal) - 1; }
    }
    __syncwarp();

    // initial global argmax
    int mid;
    {
        unsigned v = s_bm[lane];
        int vb = s_bi[lane];
        unsigned M = __reduce_max_sync(FULL, v);
        unsigned bal = __ballot_sync(FULL, v == M);
        mid = __shfl_sync(FULL, vb, __ffs(bal) - 1);
    }

    int sb0 = 0, sb1 = 0, sb2 = 0;   // stale blocks (bm in smem not yet refreshed)

    for (int t = 0; t < STEPS; t++) {
        const int nxt  = s_nxt[mid];
        const int prev = s_prv[mid];
        const int nn   = s_nxt[nxt];

        // ---- issue all row loads up front ----
        const float4* rm = (const float4*)(x + (size_t)mid * DIM);
        const float4* rn = (const float4*)(x + (size_t)nxt * DIM);
        const float4* rp = (prev >= 0) ? (const float4*)(x + (size_t)prev * DIM) : rm;
        const float4* rq = (nn   >= 0) ? (const float4*)(x + (size_t)nn   * DIM) : rm;
        float4 vm[4], vn[4], vp[4], vq[4];
        #pragma unroll
        for (int c = 0; c < 4; c++) {
            vm[c] = rm[c * 32 + lane];
            vn[c] = rn[c * 32 + lane];
            vp[c] = rp[c * 32 + lane];
            vq[c] = rq[c * 32 + lane];
        }

        // ---- issue ALL scan LDS up front (7 chains interleave under LDG shadow) ----
        const int dbm = mid >> 5;
        const int dbp = (prev >= 0 ? prev : mid) >> 5;
        const int dbn = nxt >> 5;

        unsigned bmv_l = s_bm[lane];            // register copy of block-max table
        int      bii_l = s_bi[lane];

        unsigned d0 = s_dotord[sb0 * 32 + lane];        // repair sources
        unsigned d1 = s_dotord[sb1 * 32 + lane];
        unsigned d2 = s_dotord[sb2 * 32 + lane];

        const int ep = dbp * 32 + lane;                  // rescan sources
        const int em = dbm * 32 + lane;
        const int en = dbn * 32 + lane;
        unsigned dp_ = s_dotord[ep];
        unsigned dm_ = s_dotord[em];
        unsigned dn_ = s_dotord[en];
        if (ep == prev || ep == mid || ep == nxt) dp_ = 0u;
        if (em == prev || em == mid || em == nxt) dm_ = 0u;
        if (en == prev || en == mid || en == nxt) dn_ = 0u;

        // ---- all reduces (independent chains) ----
        unsigned m0 = __reduce_max_sync(FULL, d0);
        unsigned m1 = __reduce_max_sync(FULL, d1);
        unsigned m2 = __reduce_max_sync(FULL, d2);
        unsigned mP = __reduce_max_sync(FULL, dp_);
        unsigned mM = __reduce_max_sync(FULL, dm_);
        unsigned mN = __reduce_max_sync(FULL, dn_);
        unsigned b0 = __ballot_sync(FULL, d0 == m0);
        unsigned b1 = __ballot_sync(FULL, d1 == m1);
        unsigned b2 = __ballot_sync(FULL, d2 == m2);
        unsigned bP = __ballot_sync(FULL, dp_ == mP);
        unsigned bM = __ballot_sync(FULL, dm_ == mM);
        unsigned bN = __ballot_sync(FULL, dn_ == mN);
        const int i0 = sb0 * 32 + __ffs(b0) - 1;
        const int i1 = sb1 * 32 + __ffs(b1) - 1;
        const int i2 = sb2 * 32 + __ffs(b2) - 1;
        const int iP = dbp * 32 + __ffs(bP) - 1;
        const int iM = dbm * 32 + __ffs(bM) - 1;
        const int iN = dbn * 32 + __ffs(bN) - 1;

        // substitute repaired blocks into the register table (no smem round-trip)
        if (lane == sb0) { bmv_l = m0; bii_l = i0; }
        if (lane == sb1) { bmv_l = m1; bii_l = i1; }
        if (lane == sb2) { bmv_l = m2; bii_l = i2; }

        // ---- global scan over register table, masking the dirty blocks ----
        unsigned sbv; int sbi;
        {
            unsigned v = bmv_l;
            if (lane == dbp || lane == dbm || lane == dbn) v = 0u;
            unsigned M = __reduce_max_sync(FULL, v);
            unsigned bal = __ballot_sync(FULL, v == M);
            sbi = __shfl_sync(FULL, bii_l, __ffs(bal) - 1);
            sbv = M;
        }
        // fold in dirty-block candidates (lex order: value desc, index asc)
        if (mP > sbv || (mP == sbv && iP < sbi)) { sbv = mP; sbi = iP; }
        if (mM > sbv || (mM == sbv && iM < sbi)) { sbv = mM; sbi = iM; }
        if (mN > sbv || (mN == sbv && iN < sbi)) { sbv = mN; sbi = iN; }

        // ---- merge math (bitwise-identical expressions to the passing kernels) ----
        float p1 = 0.f, p2 = 0.f;
        float4 nv[4];
        #pragma unroll
        for (int c = 0; c < 4; c++) {
            nv[c].x = 0.5f * (vm[c].x + vn[c].x);
            nv[c].y = 0.5f * (vm[c].y + vn[c].y);
            nv[c].z = 0.5f * (vm[c].z + vn[c].z);
            nv[c].w = 0.5f * (vm[c].w + vn[c].w);
            p1 += vp[c].x * nv[c].x + vp[c].y * nv[c].y + vp[c].z * nv[c].z + vp[c].w * nv[c].w;
            p2 += nv[c].x * vq[c].x + nv[c].y * vq[c].y + nv[c].z * vq[c].z + nv[c].w * vq[c].w;
        }
        float4* wrow = (float4*)(x + (size_t)mid * DIM);
        #pragma unroll
        for (int c = 0; c < 4; c++) wrow[c * 32 + lane] = nv[c];

        #pragma unroll
        for (int o = 16; o; o >>= 1) {
            p1 += __shfl_xor_sync(FULL, p1, o);
            p2 += __shfl_xor_sync(FULL, p2, o);
        }

        // ---- final selection: spec winner vs the two refreshed entries ----
        const unsigned p1o = f2ord(p1);
        const unsigned p2o = f2ord(p2);
        int newmid = sbi; unsigned newbv = sbv;
        if (prev >= 0 && (p1o > newbv || (p1o == newbv && prev < newmid))) { newbv = p1o; newmid = prev; }
        if (nn   >= 0 && (p2o > newbv || (p2o == newbv && mid  < newmid))) { newbv = p2o; newmid = mid; }

        // ---- commit: dots, links, repaired bm entries; mark new stale set ----
        if (lane == 0) {
            if (prev >= 0) s_dotord[prev] = p1o;
            s_dotord[mid] = (nn >= 0) ? p2o : 0u;
            s_dotord[nxt] = 0u;
            s_nxt[mid] = (short)nn;
            if (nn >= 0) s_prv[nn] = (short)mid;
            s_bm[sb0] = m0; s_bi[sb0] = i0;
            s_bm[sb1] = m1; s_bi[sb1] = i1;
            s_bm[sb2] = m2; s_bi[sb2] = i2;
        }
        sb0 = dbp; sb1 = dbm; sb2 = dbn;
        __syncwarp();

        mid = newmid;
    }

    // survivor order (head 0 is never removed — removed rows are always 'nxt')
    if (lane == 0) {
        int idx = 0;
        for (int c = 0; c < NCOMP; c++) { g_order[b * NCOMP + c] = idx; idx = s_nxt[idx]; }
    }
}

// ---------------- gather survivors to output (parallel) ----------------
__global__ void gather_kernel(float* __restrict__ out) {
    int r = blockIdx.x;                 // 0 .. BATCH*NCOMP-1
    int b = r / NCOMP;
    int src = g_order[r];
    const float4* s = (const float4*)(g_x + ((size_t)b * SEQ + src) * DIM);
    float4* d = (float4*)(out + (size_t)r * DIM);
    d[threadIdx.x] = s[threadIdx.x];    // 128 threads x float4 = 512 floats
}

extern "C" void kernel_launch(void* const* d_in, const int* in_sizes, int n_in,
                              void* d_out, int out_size) {
    const float* x = (const float*)d_in[0];
    float* out = (float*)d_out;
    copy_in_kernel<<<256, 256>>>(x);
    init_dots_kernel<<<(BATCH * SEQ * 32) / 256, 256>>>(x);
    merge_kernel<<<BATCH, 32>>>();
    gather_kernel<<<BATCH * NCOMP, 128>>>(out);
}